// round 4
// baseline (speedup 1.0000x reference)
#include <cuda_runtime.h>
#include <math.h>
#include <stdint.h>

// ---------------------------------------------------------------------------
// CrossModalAttention on sm_103 — tf32 mma.sync + fused flash-style attention.
//   Q/K/V projections : tf32 HMMA GEMM (A@B^T), in-frag RNA rounding of A,B,
//                       epilogue bias + RNA round (Q/K/V are tf32 values)
//   VT transpose      : per-head V^T (K-contiguous rows) for the ctx mma
//   attn_fused        : per (bh, 128-q strip):
//                         sweep1: S=QK^T recompute, l=sum exp(s*temp) in regs
//                         sweep2: S recompute, P=exp(s*temp)/l -> gmem (only
//                                 write of the 536MB tensor), rna(P)->SMEM,
//                                 ctx += P@V^T fused mma
//   out projection    : tf32 HMMA GEMM + bias (B=Wo rounded in-frag)
//   residual + LayerNorm (fp32)
// Shapes fixed: B=2, S=2048, HIDDEN=1024, HEADS=16, HDIM=64.
// ---------------------------------------------------------------------------

#define HIDDEN_ 1024
#define HEADS_  16
#define HDIM_   64
#define BATCH_  2
#define SEQ_    2048
#define MTOT_   (BATCH_*SEQ_)            // 4096

static const long long LN_N  = (long long)MTOT_ * HIDDEN_;               // 4,194,304
static const long long ATT_N = (long long)BATCH_ * HEADS_ * SEQ_ * SEQ_; // 134,217,728

// Scratch (__device__ globals: allocation-free rule)
__device__ float g_Q  [(size_t)MTOT_ * HIDDEN_];
__device__ float g_K  [(size_t)MTOT_ * HIDDEN_];
__device__ float g_V  [(size_t)MTOT_ * HIDDEN_];
__device__ float g_VT [(size_t)BATCH_ * HEADS_ * HDIM_ * SEQ_];
__device__ float g_ctx[(size_t)MTOT_ * HIDDEN_];
__device__ float g_o  [(size_t)MTOT_ * HIDDEN_];
__device__ float g_P  [(size_t)BATCH_ * HEADS_ * SEQ_ * SEQ_];  // fallback

// ---------------------------------------------------------------------------
// PTX helpers (sm_80+ portable)
// ---------------------------------------------------------------------------
__device__ __forceinline__ uint32_t smem_u32(const void* p) {
    return (uint32_t)__cvta_generic_to_shared(p);
}
__device__ __forceinline__ float rna_tf32(float x) {
    uint32_t y;
    asm("cvt.rna.tf32.f32 %0, %1;" : "=r"(y) : "f"(x));
    return __uint_as_float(y);
}
__device__ __forceinline__ void cp_async16(uint32_t dst, const void* src) {
    asm volatile("cp.async.cg.shared.global [%0], [%1], 16;" :: "r"(dst), "l"(src));
}
__device__ __forceinline__ void cp_commit() { asm volatile("cp.async.commit_group;" ::: "memory"); }
template <int N>
__device__ __forceinline__ void cp_wait_group() {
    asm volatile("cp.async.wait_group %0;" :: "n"(N) : "memory");
}
__device__ __forceinline__ void st_cs_v2(float* p, float a, float b) {
    asm volatile("st.global.cs.v2.f32 [%0], {%1,%2};" :: "l"(p), "f"(a), "f"(b) : "memory");
}
// D += A*B, m16n8k8 tf32 (HMMA on tensor pipe)
__device__ __forceinline__ void mma1688(float* d, const uint32_t* a, const uint32_t* b) {
    asm volatile(
        "mma.sync.aligned.m16n8k8.row.col.f32.tf32.tf32.f32 "
        "{%0,%1,%2,%3}, {%4,%5,%6,%7}, {%8,%9}, {%0,%1,%2,%3};"
        : "+f"(d[0]), "+f"(d[1]), "+f"(d[2]), "+f"(d[3])
        : "r"(a[0]), "r"(a[1]), "r"(a[2]), "r"(a[3]), "r"(b[0]), "r"(b[1]));
}

// ---------------------------------------------------------------------------
// tf32 mma.sync GEMM:  C[m,n] = sum_k A[m,k]*B[n,k] (+bias[n])
// RA/RB: RNA-round fragments on load. ROUND: RNA-round outputs.
// BM=128, BN=128, BK=32 floats. 256 threads = 8 warps (2x4).
// ---------------------------------------------------------------------------
template <bool RA, bool RB, bool ROUND>
__global__ void __launch_bounds__(256)
tc_gemm(const float* __restrict__ A, const float* __restrict__ Bm,
        const float* __restrict__ bias, float* __restrict__ C,
        int K, int lda, int ldb, int ldc)
{
    constexpr int BN = 128;
    constexpr int WR = 2, WC = 4;
    constexpr int WM = 64, WN = 32;
    constexpr int MT = 4, NT = 4;
    constexpr int LDS_ = 36;
    constexpr int AS_STAGE = 128 * LDS_;
    constexpr int BS_STAGE = BN * LDS_;

    extern __shared__ float sm[];
    float* As = sm;
    float* Bs = sm + 2 * AS_STAGE;

    const int tid  = threadIdx.x;
    const int warp = tid >> 5;
    const int lane = tid & 31;
    const int wr = warp % WR, wc = warp / WR;
    const int g = lane >> 2, t = lane & 3;
    const int row0 = blockIdx.y * 128;
    const int col0 = blockIdx.x * BN;

    float acc[MT][NT][4];
#pragma unroll
    for (int i = 0; i < MT; ++i)
#pragma unroll
        for (int j = 0; j < NT; ++j)
#pragma unroll
            for (int q = 0; q < 4; ++q) acc[i][j][q] = 0.0f;

    auto load_tile = [&](int kt) {
        const int st = kt & 1;
        const float* Ag = A + (size_t)row0 * lda + kt * 32;
        float* Ad = As + st * AS_STAGE;
#pragma unroll
        for (int i = 0; i < 4; ++i) {
            int id = tid + i * 256;
            int r = id >> 3, c = id & 7;
            cp_async16(smem_u32(Ad + r * LDS_ + c * 4), Ag + (size_t)r * lda + c * 4);
        }
        const float* Bg = Bm + (size_t)col0 * ldb + kt * 32;
        float* Bd = Bs + st * BS_STAGE;
#pragma unroll
        for (int i = 0; i < 4; ++i) {
            int id = tid + i * 256;
            int r = id >> 3, c = id & 7;
            cp_async16(smem_u32(Bd + r * LDS_ + c * 4), Bg + (size_t)r * ldb + c * 4);
        }
        cp_commit();
    };

    const int T = K >> 5;
    load_tile(0);
    for (int kt = 0; kt < T; ++kt) {
        if (kt + 1 < T) { load_tile(kt + 1); cp_wait_group<1>(); }
        else            { cp_wait_group<0>(); }
        __syncthreads();

        const float* Ab = As + (kt & 1) * AS_STAGE + (wr * WM) * LDS_;
        const float* Bb = Bs + (kt & 1) * BS_STAGE + (wc * WN) * LDS_;
#pragma unroll
        for (int s = 0; s < 4; ++s) {
            const int k0 = s * 8;
            uint32_t a[MT][4], b[NT][2];
#pragma unroll
            for (int i = 0; i < MT; ++i) {
                const float* ap = Ab + (i * 16 + g) * LDS_ + k0 + t;
                float a0 = ap[0], a1 = ap[8 * LDS_], a2 = ap[4], a3 = ap[8 * LDS_ + 4];
                if (RA) { a0 = rna_tf32(a0); a1 = rna_tf32(a1); a2 = rna_tf32(a2); a3 = rna_tf32(a3); }
                a[i][0] = __float_as_uint(a0);
                a[i][1] = __float_as_uint(a1);
                a[i][2] = __float_as_uint(a2);
                a[i][3] = __float_as_uint(a3);
            }
#pragma unroll
            for (int j = 0; j < NT; ++j) {
                const float* bp = Bb + (j * 8 + g) * LDS_ + k0 + t;
                float b0 = bp[0], b1 = bp[4];
                if (RB) { b0 = rna_tf32(b0); b1 = rna_tf32(b1); }
                b[j][0] = __float_as_uint(b0);
                b[j][1] = __float_as_uint(b1);
            }
#pragma unroll
            for (int i = 0; i < MT; ++i)
#pragma unroll
                for (int j = 0; j < NT; ++j)
                    mma1688(acc[i][j], a[i], b[j]);
        }
        __syncthreads();
    }

#pragma unroll
    for (int i = 0; i < MT; ++i) {
#pragma unroll
        for (int j = 0; j < NT; ++j) {
            const int r = row0 + wr * WM + i * 16 + g;
            const int c = col0 + wc * WN + j * 8 + 2 * t;
            float2 v0 = make_float2(acc[i][j][0], acc[i][j][1]);
            float2 v1 = make_float2(acc[i][j][2], acc[i][j][3]);
            if (bias) {
                const float bx = bias[c], by = bias[c + 1];
                v0.x += bx; v0.y += by;
                v1.x += bx; v1.y += by;
            }
            if (ROUND) {
                v0.x = rna_tf32(v0.x); v0.y = rna_tf32(v0.y);
                v1.x = rna_tf32(v1.x); v1.y = rna_tf32(v1.y);
            }
            *(float2*)&C[(size_t)r * ldc + c]       = v0;
            *(float2*)&C[(size_t)(r + 8) * ldc + c] = v1;
        }
    }
}

// ---------------------------------------------------------------------------
// Per-head V transpose: VT[bh][d][k] = V[b*SEQ+k][h*HDIM+d]
// ---------------------------------------------------------------------------
__global__ void __launch_bounds__(256)
transpose_v_kernel(const float* __restrict__ V, float* __restrict__ VT)
{
    __shared__ float t[32][33];
    const int bh = blockIdx.z;
    const int b = bh / HEADS_, h = bh % HEADS_;
    const int k0 = blockIdx.x * 32;
    const int d0 = blockIdx.y * 32;
    const int tx = threadIdx.x & 31;
    const int ty = threadIdx.x >> 5;
    const float* src = V + (size_t)(b * SEQ_) * HIDDEN_ + h * HDIM_;
#pragma unroll
    for (int j = 0; j < 4; ++j)
        t[ty + 8 * j][tx] = src[(size_t)(k0 + ty + 8 * j) * HIDDEN_ + d0 + tx];
    __syncthreads();
    float* dst = VT + (size_t)bh * HDIM_ * SEQ_;
#pragma unroll
    for (int j = 0; j < 4; ++j)
        dst[(size_t)(d0 + ty + 8 * j) * SEQ_ + k0 + tx] = t[tx][ty + 8 * j];
}

// ---------------------------------------------------------------------------
// Fused attention: per CTA = one (bh, 128-query strip).
//   sweep1: l_row = sum_k exp(s*temp) (register accumulation, quad+warp reduce)
//   sweep2: P = exp(s*temp)/l -> gmem (streaming) + SMEM rna(P); ctx += P@VT^T
// 256 threads = 8 warps (2 row x 4 col). Key tiles of 64. LDP=68 pad.
// ---------------------------------------------------------------------------
__global__ void __launch_bounds__(256, 1)
attn_fused(const float* __restrict__ Q, const float* __restrict__ K,
           const float* __restrict__ VT, float* __restrict__ P,
           float* __restrict__ CTX, const float* __restrict__ tptr)
{
    constexpr int LDP = 68;
    constexpr int KSTAGE = 64 * LDP;        // 4352 floats
    extern __shared__ float sm[];
    float* Qs   = sm;                        // 128*68 = 8704
    float* Ks   = sm + 8704;                 // 2*4352 = 8704
    float* Vs   = sm + 17408;                // 8704
    float* Ps   = sm + 26112;                // 8704
    float* red  = sm + 34816;                // 512
    float* invl = sm + 35328;                // 128  (total 35456 floats)

    const int strip = blockIdx.x;
    const int bh = blockIdx.y;
    const int b = bh >> 4, h = bh & 15;
    const int tid = threadIdx.x, lane = tid & 31, warp = tid >> 5;
    const int wr = warp & 1, wc = warp >> 1;
    const int g = lane >> 2, t = lane & 3;
    const float temp = *tptr;

    const float* Qg = Q + ((size_t)b * SEQ_ + strip * 128) * HIDDEN_ + h * HDIM_;
    const float* Kg = K + (size_t)b * SEQ_ * HIDDEN_ + h * HDIM_;
    const float* Vg = VT + (size_t)bh * HDIM_ * SEQ_;
    float* Pg = P + ((size_t)bh * SEQ_ + strip * 128) * SEQ_;
    float* Cg = CTX + ((size_t)b * SEQ_ + strip * 128) * HIDDEN_ + h * HDIM_;

    // Q strip 128x64 -> SMEM (group 0)
#pragma unroll
    for (int i = 0; i < 8; ++i) {
        int id = tid + i * 256;
        int r = id >> 4, c = id & 15;
        cp_async16(smem_u32(Qs + r * LDP + c * 4), Qg + (size_t)r * HIDDEN_ + c * 4);
    }
    cp_commit();

    auto loadK = [&](int kt) {
        float* dst = Ks + (kt & 1) * KSTAGE;
        const float* src = Kg + (size_t)(kt * 64) * HIDDEN_;
#pragma unroll
        for (int i = 0; i < 4; ++i) {
            int id = tid + i * 256;
            int r = id >> 4, c = id & 15;
            cp_async16(smem_u32(dst + r * LDP + c * 4), src + (size_t)r * HIDDEN_ + c * 4);
        }
    };
    auto loadV = [&](int kt) {
        float* dst = Vs + (kt & 1) * KSTAGE;
        const float* src = Vg + kt * 64;
#pragma unroll
        for (int i = 0; i < 4; ++i) {
            int id = tid + i * 256;
            int r = id >> 4, c = id & 15;
            cp_async16(smem_u32(dst + r * LDP + c * 4), src + (size_t)r * SEQ_ + c * 4);
        }
    };

    // S-tile mma: acc[MT=4][NT=2][4] over d=64 (8 k-steps)
    auto s_mma = [&](float (&acc)[4][2][4], const float* Kb) {
#pragma unroll
        for (int s = 0; s < 8; ++s) {
            const int k0 = s * 8;
            uint32_t a[4][4], bfr[2][2];
#pragma unroll
            for (int i = 0; i < 4; ++i) {
                const float* ap = Qs + (wr * 64 + i * 16 + g) * LDP + k0 + t;
                a[i][0] = __float_as_uint(ap[0]);
                a[i][1] = __float_as_uint(ap[8 * LDP]);
                a[i][2] = __float_as_uint(ap[4]);
                a[i][3] = __float_as_uint(ap[8 * LDP + 4]);
            }
#pragma unroll
            for (int j = 0; j < 2; ++j) {
                const float* bp = Kb + (wc * 16 + j * 8 + g) * LDP + k0 + t;
                bfr[j][0] = __float_as_uint(bp[0]);
                bfr[j][1] = __float_as_uint(bp[4]);
            }
#pragma unroll
            for (int i = 0; i < 4; ++i)
#pragma unroll
                for (int j = 0; j < 2; ++j)
                    mma1688(acc[i][j], a[i], bfr[j]);
        }
    };

    // ---------------- Sweep 1: row sums of exp(s*temp) ----------------
    float rs[4][2];
#pragma unroll
    for (int i = 0; i < 4; ++i) { rs[i][0] = 0.f; rs[i][1] = 0.f; }

    loadK(0); cp_commit();
    for (int kt = 0; kt < 32; ++kt) {
        if (kt + 1 < 32) { loadK(kt + 1); cp_commit(); cp_wait_group<1>(); }
        else             { cp_wait_group<0>(); }
        __syncthreads();
        const float* Kb = Ks + (kt & 1) * KSTAGE;
        float acc[4][2][4];
#pragma unroll
        for (int i = 0; i < 4; ++i)
#pragma unroll
            for (int j = 0; j < 2; ++j)
#pragma unroll
                for (int q = 0; q < 4; ++q) acc[i][j][q] = 0.f;
        s_mma(acc, Kb);
#pragma unroll
        for (int i = 0; i < 4; ++i)
#pragma unroll
            for (int j = 0; j < 2; ++j) {
                rs[i][0] += __expf(acc[i][j][0] * temp) + __expf(acc[i][j][1] * temp);
                rs[i][1] += __expf(acc[i][j][2] * temp) + __expf(acc[i][j][3] * temp);
            }
        __syncthreads();
    }

    // reduce across quad (t) then across wc warps via SMEM
#pragma unroll
    for (int i = 0; i < 4; ++i)
#pragma unroll
        for (int r01 = 0; r01 < 2; ++r01) {
            float v = rs[i][r01];
            v += __shfl_xor_sync(0xffffffffu, v, 1);
            v += __shfl_xor_sync(0xffffffffu, v, 2);
            rs[i][r01] = v;
        }
    if (t == 0) {
#pragma unroll
        for (int i = 0; i < 4; ++i) {
            red[wc * 128 + wr * 64 + i * 16 + g]     = rs[i][0];
            red[wc * 128 + wr * 64 + i * 16 + g + 8] = rs[i][1];
        }
    }
    __syncthreads();
    if (tid < 128)
        invl[tid] = 1.0f / (red[tid] + red[128 + tid] + red[256 + tid] + red[384 + tid]);
    __syncthreads();

    float linv[4][2];
#pragma unroll
    for (int i = 0; i < 4; ++i) {
        linv[i][0] = invl[wr * 64 + i * 16 + g];
        linv[i][1] = invl[wr * 64 + i * 16 + g + 8];
    }

    // ---------------- Sweep 2: P write + fused ctx ----------------
    float ctx[4][2][4];
#pragma unroll
    for (int i = 0; i < 4; ++i)
#pragma unroll
        for (int j = 0; j < 2; ++j)
#pragma unroll
            for (int q = 0; q < 4; ++q) ctx[i][j][q] = 0.f;

    loadK(0); loadV(0); cp_commit();
    for (int kt = 0; kt < 32; ++kt) {
        if (kt + 1 < 32) { loadK(kt + 1); loadV(kt + 1); cp_commit(); cp_wait_group<1>(); }
        else             { cp_wait_group<0>(); }
        __syncthreads();
        const float* Kb = Ks + (kt & 1) * KSTAGE;
        const float* Vb = Vs + (kt & 1) * KSTAGE;

        float acc[4][2][4];
#pragma unroll
        for (int i = 0; i < 4; ++i)
#pragma unroll
            for (int j = 0; j < 2; ++j)
#pragma unroll
                for (int q = 0; q < 4; ++q) acc[i][j][q] = 0.f;
        s_mma(acc, Kb);

        // normalize + store (gmem streaming fp32, SMEM rna)
#pragma unroll
        for (int i = 0; i < 4; ++i) {
            const int rA = wr * 64 + i * 16 + g;
#pragma unroll
            for (int j = 0; j < 2; ++j) {
                const int col = wc * 16 + j * 8 + 2 * t;
                float p0 = __expf(acc[i][j][0] * temp) * linv[i][0];
                float p1 = __expf(acc[i][j][1] * temp) * linv[i][0];
                float p2 = __expf(acc[i][j][2] * temp) * linv[i][1];
                float p3 = __expf(acc[i][j][3] * temp) * linv[i][1];
                st_cs_v2(Pg + (size_t)rA * SEQ_ + kt * 64 + col, p0, p1);
                st_cs_v2(Pg + (size_t)(rA + 8) * SEQ_ + kt * 64 + col, p2, p3);
                *(float2*)(Ps + rA * LDP + col)       = make_float2(rna_tf32(p0), rna_tf32(p1));
                *(float2*)(Ps + (rA + 8) * LDP + col) = make_float2(rna_tf32(p2), rna_tf32(p3));
            }
        }
        __syncthreads();

        // ctx += Ptile(128x64) @ VT_tile(64d x 64k)^T
#pragma unroll
        for (int s = 0; s < 8; ++s) {
            const int kk = s * 8;
            uint32_t a[4][4], bfr[2][2];
#pragma unroll
            for (int i = 0; i < 4; ++i) {
                const float* ap = Ps + (wr * 64 + i * 16 + g) * LDP + kk + t;
                a[i][0] = __float_as_uint(ap[0]);
                a[i][1] = __float_as_uint(ap[8 * LDP]);
                a[i][2] = __float_as_uint(ap[4]);
                a[i][3] = __float_as_uint(ap[8 * LDP + 4]);
            }
#pragma unroll
            for (int j = 0; j < 2; ++j) {
                const float* bp = Vb + (wc * 16 + j * 8 + g) * LDP + kk + t;
                bfr[j][0] = __float_as_uint(bp[0]);
                bfr[j][1] = __float_as_uint(bp[4]);
            }
#pragma unroll
            for (int i = 0; i < 4; ++i)
#pragma unroll
                for (int j = 0; j < 2; ++j)
                    mma1688(ctx[i][j], a[i], bfr[j]);
        }
        __syncthreads();
    }

    // write ctx (RNA-rounded: feeds out-projection GEMM)
#pragma unroll
    for (int i = 0; i < 4; ++i) {
        const int rA = wr * 64 + i * 16 + g;
#pragma unroll
        for (int j = 0; j < 2; ++j) {
            const int col = wc * 16 + j * 8 + 2 * t;
            *(float2*)(Cg + (size_t)rA * HIDDEN_ + col) =
                make_float2(rna_tf32(ctx[i][j][0]), rna_tf32(ctx[i][j][1]));
            *(float2*)(Cg + (size_t)(rA + 8) * HIDDEN_ + col) =
                make_float2(rna_tf32(ctx[i][j][2]), rna_tf32(ctx[i][j][3]));
        }
    }
}

// ---------------------------------------------------------------------------
// Residual + LayerNorm (fp32)
// ---------------------------------------------------------------------------
__global__ void __launch_bounds__(256)
ln_kernel(const float* __restrict__ o, const float* __restrict__ resid,
          const float* __restrict__ gamma, const float* __restrict__ beta,
          float* __restrict__ out)
{
    __shared__ float red1[8], red2[8];
    __shared__ float bmean, binv;

    const size_t row = blockIdx.x;
    const int tid = threadIdx.x;
    const int lane = tid & 31, wid = tid >> 5;
    const float* po = o + row * HIDDEN_;
    const float* pr = resid + row * HIDDEN_;

    float x[4];
    float s = 0.0f, s2 = 0.0f;
#pragma unroll
    for (int u = 0; u < 4; ++u) {
        const int idx = tid + 256 * u;
        x[u] = po[idx] + pr[idx];
        s += x[u];
        s2 += x[u] * x[u];
    }
#pragma unroll
    for (int of = 16; of; of >>= 1) {
        s  += __shfl_xor_sync(0xffffffffu, s,  of);
        s2 += __shfl_xor_sync(0xffffffffu, s2, of);
    }
    if (lane == 0) { red1[wid] = s; red2[wid] = s2; }
    __syncthreads();
    if (wid == 0) {
        float t1 = (lane < 8) ? red1[lane] : 0.0f;
        float t2 = (lane < 8) ? red2[lane] : 0.0f;
#pragma unroll
        for (int of = 16; of; of >>= 1) {
            t1 += __shfl_xor_sync(0xffffffffu, t1, of);
            t2 += __shfl_xor_sync(0xffffffffu, t2, of);
        }
        if (lane == 0) {
            const float mean = t1 * (1.0f / HIDDEN_);
            const float var  = t2 * (1.0f / HIDDEN_) - mean * mean;
            bmean = mean;
            binv  = rsqrtf(var + 1e-5f);
        }
    }
    __syncthreads();
    const float mean = bmean, inv = binv;
#pragma unroll
    for (int u = 0; u < 4; ++u) {
        const int idx = tid + 256 * u;
        out[row * HIDDEN_ + idx] = (x[u] - mean) * inv * gamma[idx] + beta[idx];
    }
}

// ---------------------------------------------------------------------------
static const int DSM_GEMM = 2 * (128 + 128) * 36 * 4;   // 73728
static const int DSM_ATTN = 35456 * 4;                  // 141824

extern "C" void kernel_launch(void* const* d_in, const int* in_sizes, int n_in,
                              void* d_out, int out_size)
{
    const float* query = (const float*)d_in[0];
    const float* key_  = (const float*)d_in[1];
    const float* value = (const float*)d_in[2];
    const float* Wq = (const float*)d_in[3];
    const float* bq = (const float*)d_in[4];
    const float* Wk = (const float*)d_in[5];
    const float* bk = (const float*)d_in[6];
    const float* Wv = (const float*)d_in[7];
    const float* bv = (const float*)d_in[8];
    const float* Wo = (const float*)d_in[9];
    const float* bo = (const float*)d_in[10];
    const float* gamma = (const float*)d_in[11];
    const float* beta  = (const float*)d_in[12];
    const float* temp  = (const float*)d_in[13];

    cudaFuncSetAttribute(tc_gemm<true,  true, true >, cudaFuncAttributeMaxDynamicSharedMemorySize, DSM_GEMM);
    cudaFuncSetAttribute(tc_gemm<false, true, false>, cudaFuncAttributeMaxDynamicSharedMemorySize, DSM_GEMM);
    cudaFuncSetAttribute(attn_fused, cudaFuncAttributeMaxDynamicSharedMemorySize, DSM_ATTN);

    float* out_ln = (float*)d_out;
    float *pQ, *pK, *pV, *pVT, *pCtx, *pO, *pP;
    cudaGetSymbolAddress((void**)&pQ,   g_Q);
    cudaGetSymbolAddress((void**)&pK,   g_K);
    cudaGetSymbolAddress((void**)&pV,   g_V);
    cudaGetSymbolAddress((void**)&pVT,  g_VT);
    cudaGetSymbolAddress((void**)&pCtx, g_ctx);
    cudaGetSymbolAddress((void**)&pO,   g_o);
    if ((long long)out_size >= LN_N + ATT_N) {
        pP = out_ln + LN_N;           // attn_weights are part of the output
    } else {
        cudaGetSymbolAddress((void**)&pP, g_P);
    }

    // --- Projections: X @ W^T + b (in-frag RNA on A,B; outputs RNA-rounded)
    {
        dim3 g(HIDDEN_ / 128, MTOT_ / 128, 1);
        tc_gemm<true, true, true><<<g, 256, DSM_GEMM>>>(query, Wq, bq, pQ,
            HIDDEN_, HIDDEN_, HIDDEN_, HIDDEN_);
        tc_gemm<true, true, true><<<g, 256, DSM_GEMM>>>(key_,  Wk, bk, pK,
            HIDDEN_, HIDDEN_, HIDDEN_, HIDDEN_);
        tc_gemm<true, true, true><<<g, 256, DSM_GEMM>>>(value, Wv, bv, pV,
            HIDDEN_, HIDDEN_, HIDDEN_, HIDDEN_);
    }

    // --- VT: per-head transpose of V
    {
        dim3 g(SEQ_ / 32, HDIM_ / 32, BATCH_ * HEADS_);
        transpose_v_kernel<<<g, 256>>>(pV, pVT);
    }

    // --- Fused attention: stats + P write + context
    {
        dim3 g(SEQ_ / 128, BATCH_ * HEADS_, 1);
        attn_fused<<<g, 256, DSM_ATTN>>>(pQ, pK, pVT, pP, pCtx, temp);
    }

    // --- Output projection: o = ctx @ Wo^T + bo (ctx already tf32; round Wo)
    {
        dim3 g(HIDDEN_ / 128, MTOT_ / 128, 1);
        tc_gemm<false, true, false><<<g, 256, DSM_GEMM>>>(pCtx, Wo, bo, pO,
            HIDDEN_, HIDDEN_, HIDDEN_, HIDDEN_);
    }

    // --- Residual + LayerNorm
    ln_kernel<<<(unsigned)MTOT_, 256>>>(pO, query, gamma, beta, out_ln);
}

// round 5
// speedup vs baseline: 1.0999x; 1.0999x over previous
#include <cuda_runtime.h>
#include <math.h>
#include <stdint.h>

// ---------------------------------------------------------------------------
// CrossModalAttention on sm_103 — tf32 mma.sync pipeline, softmax folded into
// scores-epilogue (exp + deterministic partial sums) and context-prologue
// (stream normalize + final P write).
//   Q/K/V projections : tf32 HMMA GEMM (A@B^T), in-frag RNA, bias, RNA out
//   VT transpose      : per-head V^T (k-contiguous) for ctx mma
//   scores_exp        : E = exp((Q K^T)*temp) -> gmem; per-CTA row sums -> PS
//   inv_reduce        : invl = 1/sum(PS)
//   ctx_fused         : stream E, P = E*invl -> gmem (attn output),
//                       rna(P) -> SMEM, ctx += P @ VT^T
//   out projection    : tf32 HMMA GEMM + bias
//   residual + LayerNorm (fp32)
// Shapes fixed: B=2, S=2048, HIDDEN=1024, HEADS=16, HDIM=64.
// ---------------------------------------------------------------------------

#define HIDDEN_ 1024
#define HEADS_  16
#define HDIM_   64
#define BATCH_  2
#define SEQ_    2048
#define MTOT_   (BATCH_*SEQ_)            // 4096
#define NROWS_  (BATCH_*HEADS_*SEQ_)     // 65536 attention rows

static const long long LN_N  = (long long)MTOT_ * HIDDEN_;               // 4,194,304
static const long long ATT_N = (long long)BATCH_ * HEADS_ * SEQ_ * SEQ_; // 134,217,728

// Scratch (__device__ globals: allocation-free rule)
__device__ float g_Q  [(size_t)MTOT_ * HIDDEN_];
__device__ float g_K  [(size_t)MTOT_ * HIDDEN_];
__device__ float g_V  [(size_t)MTOT_ * HIDDEN_];
__device__ float g_VT [(size_t)BATCH_ * HEADS_ * HDIM_ * SEQ_];
__device__ float g_ctx[(size_t)MTOT_ * HIDDEN_];
__device__ float g_o  [(size_t)MTOT_ * HIDDEN_];
__device__ float g_E  [(size_t)BATCH_ * HEADS_ * SEQ_ * SEQ_];  // exp(s*temp)
__device__ float g_PS [(size_t)NROWS_ * 16];                    // partial sums
__device__ float g_INV[(size_t)NROWS_];                         // 1/l

// ---------------------------------------------------------------------------
// PTX helpers (sm_80+ portable)
// ---------------------------------------------------------------------------
__device__ __forceinline__ uint32_t smem_u32(const void* p) {
    return (uint32_t)__cvta_generic_to_shared(p);
}
__device__ __forceinline__ float rna_tf32(float x) {
    uint32_t y;
    asm("cvt.rna.tf32.f32 %0, %1;" : "=r"(y) : "f"(x));
    return __uint_as_float(y);
}
__device__ __forceinline__ void cp_async16(uint32_t dst, const void* src) {
    asm volatile("cp.async.cg.shared.global [%0], [%1], 16;" :: "r"(dst), "l"(src));
}
__device__ __forceinline__ void cp_commit() { asm volatile("cp.async.commit_group;" ::: "memory"); }
template <int N>
__device__ __forceinline__ void cp_wait_group() {
    asm volatile("cp.async.wait_group %0;" :: "n"(N) : "memory");
}
__device__ __forceinline__ void st_cs_v2(float* p, float a, float b) {
    asm volatile("st.global.cs.v2.f32 [%0], {%1,%2};" :: "l"(p), "f"(a), "f"(b) : "memory");
}
__device__ __forceinline__ void st_cs_v4(float* p, float4 v) {
    asm volatile("st.global.cs.v4.f32 [%0], {%1,%2,%3,%4};"
                 :: "l"(p), "f"(v.x), "f"(v.y), "f"(v.z), "f"(v.w) : "memory");
}
__device__ __forceinline__ float4 ld_cs_v4(const float* p) {
    float4 v;
    asm volatile("ld.global.cs.v4.f32 {%0,%1,%2,%3}, [%4];"
                 : "=f"(v.x), "=f"(v.y), "=f"(v.z), "=f"(v.w) : "l"(p));
    return v;
}
// D += A*B, m16n8k8 tf32 (HMMA on tensor pipe)
__device__ __forceinline__ void mma1688(float* d, const uint32_t* a, const uint32_t* b) {
    asm volatile(
        "mma.sync.aligned.m16n8k8.row.col.f32.tf32.tf32.f32 "
        "{%0,%1,%2,%3}, {%4,%5,%6,%7}, {%8,%9}, {%0,%1,%2,%3};"
        : "+f"(d[0]), "+f"(d[1]), "+f"(d[2]), "+f"(d[3])
        : "r"(a[0]), "r"(a[1]), "r"(a[2]), "r"(a[3]), "r"(b[0]), "r"(b[1]));
}

// ---------------------------------------------------------------------------
// tf32 mma.sync GEMM:  C[m,n] = sum_k A[m,k]*B[n,k] (+bias[n])
// RA/RB: RNA-round fragments on load. ROUND: RNA-round outputs.
// BM=128, BN=128, BK=32 floats. 256 threads = 8 warps (2x4).
// ---------------------------------------------------------------------------
template <bool RA, bool RB, bool ROUND>
__global__ void __launch_bounds__(256)
tc_gemm(const float* __restrict__ A, const float* __restrict__ Bm,
        const float* __restrict__ bias, float* __restrict__ C,
        int K, int lda, int ldb, int ldc)
{
    constexpr int LDS_ = 36;
    constexpr int AS_STAGE = 128 * LDS_;
    constexpr int BS_STAGE = 128 * LDS_;

    extern __shared__ float sm[];
    float* As = sm;
    float* Bs = sm + 2 * AS_STAGE;

    const int tid  = threadIdx.x;
    const int warp = tid >> 5;
    const int lane = tid & 31;
    const int wr = warp & 1, wc = warp >> 1;
    const int g = lane >> 2, t = lane & 3;
    const int row0 = blockIdx.y * 128;
    const int col0 = blockIdx.x * 128;

    float acc[4][4][4];
#pragma unroll
    for (int i = 0; i < 4; ++i)
#pragma unroll
        for (int j = 0; j < 4; ++j)
#pragma unroll
            for (int q = 0; q < 4; ++q) acc[i][j][q] = 0.0f;

    auto load_tile = [&](int kt) {
        const int st = kt & 1;
        const float* Ag = A + (size_t)row0 * lda + kt * 32;
        float* Ad = As + st * AS_STAGE;
#pragma unroll
        for (int i = 0; i < 4; ++i) {
            int id = tid + i * 256;
            int r = id >> 3, c = id & 7;
            cp_async16(smem_u32(Ad + r * LDS_ + c * 4), Ag + (size_t)r * lda + c * 4);
        }
        const float* Bg = Bm + (size_t)col0 * ldb + kt * 32;
        float* Bd = Bs + st * BS_STAGE;
#pragma unroll
        for (int i = 0; i < 4; ++i) {
            int id = tid + i * 256;
            int r = id >> 3, c = id & 7;
            cp_async16(smem_u32(Bd + r * LDS_ + c * 4), Bg + (size_t)r * ldb + c * 4);
        }
        cp_commit();
    };

    const int T = K >> 5;
    load_tile(0);
    for (int kt = 0; kt < T; ++kt) {
        if (kt + 1 < T) { load_tile(kt + 1); cp_wait_group<1>(); }
        else            { cp_wait_group<0>(); }
        __syncthreads();

        const float* Ab = As + (kt & 1) * AS_STAGE + (wr * 64) * LDS_;
        const float* Bb = Bs + (kt & 1) * BS_STAGE + (wc * 32) * LDS_;
#pragma unroll
        for (int s = 0; s < 4; ++s) {
            const int k0 = s * 8;
            uint32_t a[4][4], b[4][2];
#pragma unroll
            for (int i = 0; i < 4; ++i) {
                const float* ap = Ab + (i * 16 + g) * LDS_ + k0 + t;
                float a0 = ap[0], a1 = ap[8 * LDS_], a2 = ap[4], a3 = ap[8 * LDS_ + 4];
                if (RA) { a0 = rna_tf32(a0); a1 = rna_tf32(a1); a2 = rna_tf32(a2); a3 = rna_tf32(a3); }
                a[i][0] = __float_as_uint(a0);
                a[i][1] = __float_as_uint(a1);
                a[i][2] = __float_as_uint(a2);
                a[i][3] = __float_as_uint(a3);
            }
#pragma unroll
            for (int j = 0; j < 4; ++j) {
                const float* bp = Bb + (j * 8 + g) * LDS_ + k0 + t;
                float b0 = bp[0], b1 = bp[4];
                if (RB) { b0 = rna_tf32(b0); b1 = rna_tf32(b1); }
                b[j][0] = __float_as_uint(b0);
                b[j][1] = __float_as_uint(b1);
            }
#pragma unroll
            for (int i = 0; i < 4; ++i)
#pragma unroll
                for (int j = 0; j < 4; ++j)
                    mma1688(acc[i][j], a[i], b[j]);
        }
        __syncthreads();
    }

#pragma unroll
    for (int i = 0; i < 4; ++i) {
#pragma unroll
        for (int j = 0; j < 4; ++j) {
            const int r = row0 + wr * 64 + i * 16 + g;
            const int c = col0 + wc * 32 + j * 8 + 2 * t;
            float2 v0 = make_float2(acc[i][j][0], acc[i][j][1]);
            float2 v1 = make_float2(acc[i][j][2], acc[i][j][3]);
            if (bias) {
                const float bx = bias[c], by = bias[c + 1];
                v0.x += bx; v0.y += by;
                v1.x += bx; v1.y += by;
            }
            if (ROUND) {
                v0.x = rna_tf32(v0.x); v0.y = rna_tf32(v0.y);
                v1.x = rna_tf32(v1.x); v1.y = rna_tf32(v1.y);
            }
            *(float2*)&C[(size_t)r * ldc + c]       = v0;
            *(float2*)&C[(size_t)(r + 8) * ldc + c] = v1;
        }
    }
}

// ---------------------------------------------------------------------------
// Per-head V transpose: VT[bh][d][k] = V[b*SEQ+k][h*HDIM+d]
// ---------------------------------------------------------------------------
__global__ void __launch_bounds__(256)
transpose_v_kernel(const float* __restrict__ V, float* __restrict__ VT)
{
    __shared__ float t[32][33];
    const int bh = blockIdx.z;
    const int b = bh / HEADS_, h = bh % HEADS_;
    const int k0 = blockIdx.x * 32;
    const int d0 = blockIdx.y * 32;
    const int tx = threadIdx.x & 31;
    const int ty = threadIdx.x >> 5;
    const float* src = V + (size_t)(b * SEQ_) * HIDDEN_ + h * HDIM_;
#pragma unroll
    for (int j = 0; j < 4; ++j)
        t[ty + 8 * j][tx] = src[(size_t)(k0 + ty + 8 * j) * HIDDEN_ + d0 + tx];
    __syncthreads();
    float* dst = VT + (size_t)bh * HDIM_ * SEQ_;
#pragma unroll
    for (int j = 0; j < 4; ++j)
        dst[(size_t)(d0 + ty + 8 * j) * SEQ_ + k0 + tx] = t[tx][ty + 8 * j];
}

// ---------------------------------------------------------------------------
// Scores + exp: per CTA = 128x128 tile of one (bh).  K = 64 (single stage).
// E[tile] = exp(S*temp) streamed out; per-row partial sums -> PS[row][bx].
// 256 threads = 8 warps (2 row x 4 col). LDP=68 pad.
// ---------------------------------------------------------------------------
__global__ void __launch_bounds__(256)
scores_exp_kernel(const float* __restrict__ Q, const float* __restrict__ K,
                  float* __restrict__ E, float* __restrict__ PS,
                  const float* __restrict__ tptr)
{
    constexpr int LDP = 68;
    extern __shared__ float sm[];
    float* Qs = sm;                 // 128*68
    float* Ks = sm + 128 * LDP;     // 128*68
    __shared__ float red[512];

    const int bx = blockIdx.x;      // key block (0..15)
    const int by = blockIdx.y;      // query block (0..15)
    const int bh = blockIdx.z;
    const int b = bh >> 4, h = bh & 15;
    const int tid = threadIdx.x, lane = tid & 31, warp = tid >> 5;
    const int wr = warp & 1, wc = warp >> 1;
    const int g = lane >> 2, t = lane & 3;
    const float temp = *tptr;

    const float* Qg = Q + ((size_t)(b * SEQ_) + by * 128) * HIDDEN_ + h * HDIM_;
    const float* Kg = K + ((size_t)(b * SEQ_) + bx * 128) * HIDDEN_ + h * HDIM_;
    float* Eg = E + ((size_t)bh * SEQ_ + by * 128) * SEQ_ + bx * 128;

#pragma unroll
    for (int i = 0; i < 8; ++i) {
        int id = tid + i * 256;
        int r = id >> 4, c = id & 15;
        cp_async16(smem_u32(Qs + r * LDP + c * 4), Qg + (size_t)r * HIDDEN_ + c * 4);
    }
#pragma unroll
    for (int i = 0; i < 8; ++i) {
        int id = tid + i * 256;
        int r = id >> 4, c = id & 15;
        cp_async16(smem_u32(Ks + r * LDP + c * 4), Kg + (size_t)r * HIDDEN_ + c * 4);
    }
    cp_commit();
    cp_wait_group<0>();
    __syncthreads();

    float acc[4][4][4];
#pragma unroll
    for (int i = 0; i < 4; ++i)
#pragma unroll
        for (int j = 0; j < 4; ++j)
#pragma unroll
            for (int q = 0; q < 4; ++q) acc[i][j][q] = 0.0f;

#pragma unroll
    for (int s = 0; s < 8; ++s) {
        const int k0 = s * 8;
        uint32_t a[4][4], bf[4][2];
#pragma unroll
        for (int i = 0; i < 4; ++i) {
            const float* ap = Qs + (wr * 64 + i * 16 + g) * LDP + k0 + t;
            a[i][0] = __float_as_uint(ap[0]);
            a[i][1] = __float_as_uint(ap[8 * LDP]);
            a[i][2] = __float_as_uint(ap[4]);
            a[i][3] = __float_as_uint(ap[8 * LDP + 4]);
        }
#pragma unroll
        for (int j = 0; j < 4; ++j) {
            const float* bp = Ks + (wc * 32 + j * 8 + g) * LDP + k0 + t;
            bf[j][0] = __float_as_uint(bp[0]);
            bf[j][1] = __float_as_uint(bp[4]);
        }
#pragma unroll
        for (int i = 0; i < 4; ++i)
#pragma unroll
            for (int j = 0; j < 4; ++j)
                mma1688(acc[i][j], a[i], bf[j]);
    }

    // exp + store E + per-row sums
    float rs0[4], rs1[4];
#pragma unroll
    for (int i = 0; i < 4; ++i) { rs0[i] = 0.f; rs1[i] = 0.f; }
#pragma unroll
    for (int i = 0; i < 4; ++i) {
        const int rA = wr * 64 + i * 16 + g;
#pragma unroll
        for (int j = 0; j < 4; ++j) {
            const int c = wc * 32 + j * 8 + 2 * t;
            float e0 = __expf(acc[i][j][0] * temp);
            float e1 = __expf(acc[i][j][1] * temp);
            float e2 = __expf(acc[i][j][2] * temp);
            float e3 = __expf(acc[i][j][3] * temp);
            st_cs_v2(Eg + (size_t)rA * SEQ_ + c, e0, e1);
            st_cs_v2(Eg + (size_t)(rA + 8) * SEQ_ + c, e2, e3);
            rs0[i] += e0 + e1;
            rs1[i] += e2 + e3;
        }
    }
    // quad reduce across t (lanes xor 1,2)
#pragma unroll
    for (int i = 0; i < 4; ++i) {
        rs0[i] += __shfl_xor_sync(0xffffffffu, rs0[i], 1);
        rs0[i] += __shfl_xor_sync(0xffffffffu, rs0[i], 2);
        rs1[i] += __shfl_xor_sync(0xffffffffu, rs1[i], 1);
        rs1[i] += __shfl_xor_sync(0xffffffffu, rs1[i], 2);
    }
    if (t == 0) {
#pragma unroll
        for (int i = 0; i < 4; ++i) {
            red[wc * 128 + wr * 64 + i * 16 + g]     = rs0[i];
            red[wc * 128 + wr * 64 + i * 16 + g + 8] = rs1[i];
        }
    }
    __syncthreads();
    if (tid < 128) {
        float s = red[tid] + red[128 + tid] + red[256 + tid] + red[384 + tid];
        PS[((size_t)bh * SEQ_ + by * 128 + tid) * 16 + bx] = s;
    }
}

// ---------------------------------------------------------------------------
// invl[row] = 1 / sum of 16 partials
// ---------------------------------------------------------------------------
__global__ void __launch_bounds__(256)
inv_reduce_kernel(const float* __restrict__ PS, float* __restrict__ INV)
{
    const int i = blockIdx.x * 256 + threadIdx.x;   // 65536 rows
    const float4* p = (const float4*)(PS + (size_t)i * 16);
    float4 a = p[0], b = p[1], c = p[2], d = p[3];
    float s = (a.x + a.y + a.z + a.w) + (b.x + b.y + b.z + b.w)
            + (c.x + c.y + c.z + c.w) + (d.x + d.y + d.z + d.w);
    INV[i] = 1.0f / s;
}

// ---------------------------------------------------------------------------
// Context fused: per CTA = (bh, 128-row strip). K = 2048, BK=32, BN=64.
// Streams E, writes P = E*invl (attn output), rna(P)->SMEM, ctx += P@VT^T.
// 256 threads = 8 warps (2 row x 4 col; WN=16).
// ---------------------------------------------------------------------------
__global__ void __launch_bounds__(256)
ctx_fused_kernel(const float* __restrict__ E, const float* __restrict__ INV,
                 const float* __restrict__ VT, float* __restrict__ P,
                 float* __restrict__ CTX)
{
    constexpr int LDS_ = 36;
    constexpr int AS_STAGE = 128 * LDS_;   // 4608
    constexpr int BS_STAGE = 64 * LDS_;    // 2304
    extern __shared__ float sm[];
    float* As = sm;                        // 2 stages
    float* Bs = sm + 2 * AS_STAGE;         // 2 stages
    __shared__ float s_inv[128];

    const int strip = blockIdx.x;
    const int bh = blockIdx.y;
    const int b = bh >> 4, h = bh & 15;
    const int tid = threadIdx.x, lane = tid & 31, warp = tid >> 5;
    const int wr = warp & 1, wc = warp >> 1;
    const int g = lane >> 2, t = lane & 3;

    const float* Eg = E + ((size_t)bh * SEQ_ + strip * 128) * SEQ_;
    float*       Pg = P + ((size_t)bh * SEQ_ + strip * 128) * SEQ_;
    const float* Vg = VT + (size_t)bh * HDIM_ * SEQ_;
    float*       Cg = CTX + ((size_t)(b * SEQ_) + strip * 128) * HIDDEN_ + h * HDIM_;

    if (tid < 128) s_inv[tid] = INV[(size_t)bh * SEQ_ + strip * 128 + tid];

    float4 cur[4];
    auto ldgA = [&](int kt, float4* dst) {
#pragma unroll
        for (int i = 0; i < 4; ++i) {
            int idx = tid + i * 256;
            int r = idx >> 3, c = idx & 7;
            dst[i] = ld_cs_v4(Eg + (size_t)r * SEQ_ + kt * 32 + c * 4);
        }
    };
    auto loadB = [&](int kt) {
        float* Bd = Bs + (kt & 1) * BS_STAGE;
#pragma unroll
        for (int i = 0; i < 2; ++i) {
            int id = tid + i * 256;
            int r = id >> 3, c = id & 7;
            cp_async16(smem_u32(Bd + r * LDS_ + c * 4), Vg + (size_t)r * SEQ_ + kt * 32 + c * 4);
        }
        cp_commit();
    };
    auto procA = [&](int kt, float4* v) {
        float* Ad = As + (kt & 1) * AS_STAGE;
#pragma unroll
        for (int i = 0; i < 4; ++i) {
            int idx = tid + i * 256;
            int r = idx >> 3, c = idx & 7;
            const float inv = s_inv[r];
            float4 p;
            p.x = v[i].x * inv; p.y = v[i].y * inv;
            p.z = v[i].z * inv; p.w = v[i].w * inv;
            st_cs_v4(Pg + (size_t)r * SEQ_ + kt * 32 + c * 4, p);
            float4 q;
            q.x = rna_tf32(p.x); q.y = rna_tf32(p.y);
            q.z = rna_tf32(p.z); q.w = rna_tf32(p.w);
            *(float4*)(Ad + r * LDS_ + c * 4) = q;
        }
    };

    float ctx[4][2][4];
#pragma unroll
    for (int i = 0; i < 4; ++i)
#pragma unroll
        for (int j = 0; j < 2; ++j)
#pragma unroll
            for (int q = 0; q < 4; ++q) ctx[i][j][q] = 0.f;

    ldgA(0, cur);
    loadB(0);
    __syncthreads();             // s_inv visible

    for (int kt = 0; kt < 64; ++kt) {
        procA(kt, cur);          // As[kt&1]: last read by mma kt-2 (sync-protected)
        cp_wait_group<0>();      // B tile kt landed
        __syncthreads();         // STS visible; mma kt-1 done everywhere
        if (kt + 1 < 64) {       // safe to touch (kt+1)&1 buffers now
            ldgA(kt + 1, cur);
            loadB(kt + 1);
        }
        const float* Ab = As + (kt & 1) * AS_STAGE + (wr * 64) * LDS_;
        const float* Bb = Bs + (kt & 1) * BS_STAGE + (wc * 16) * LDS_;
#pragma unroll
        for (int s = 0; s < 4; ++s) {
            const int k0 = s * 8;
            uint32_t a[4][4], bf[2][2];
#pragma unroll
            for (int i = 0; i < 4; ++i) {
                const float* ap = Ab + (i * 16 + g) * LDS_ + k0 + t;
                a[i][0] = __float_as_uint(ap[0]);
                a[i][1] = __float_as_uint(ap[8 * LDS_]);
                a[i][2] = __float_as_uint(ap[4]);
                a[i][3] = __float_as_uint(ap[8 * LDS_ + 4]);
            }
#pragma unroll
            for (int j = 0; j < 2; ++j) {
                const float* bp = Bb + (j * 8 + g) * LDS_ + k0 + t;
                bf[j][0] = __float_as_uint(bp[0]);
                bf[j][1] = __float_as_uint(bp[4]);
            }
#pragma unroll
            for (int i = 0; i < 4; ++i)
#pragma unroll
                for (int j = 0; j < 2; ++j)
                    mma1688(ctx[i][j], a[i], bf[j]);
        }
        __syncthreads();
    }

    // write ctx (RNA: feeds out-projection GEMM)
#pragma unroll
    for (int i = 0; i < 4; ++i) {
        const int rA = wr * 64 + i * 16 + g;
#pragma unroll
        for (int j = 0; j < 2; ++j) {
            const int c = wc * 16 + j * 8 + 2 * t;
            *(float2*)(Cg + (size_t)rA * HIDDEN_ + c) =
                make_float2(rna_tf32(ctx[i][j][0]), rna_tf32(ctx[i][j][1]));
            *(float2*)(Cg + (size_t)(rA + 8) * HIDDEN_ + c) =
                make_float2(rna_tf32(ctx[i][j][2]), rna_tf32(ctx[i][j][3]));
        }
    }
}

// ---------------------------------------------------------------------------
// Residual + LayerNorm (fp32)
// ---------------------------------------------------------------------------
__global__ void __launch_bounds__(256)
ln_kernel(const float* __restrict__ o, const float* __restrict__ resid,
          const float* __restrict__ gamma, const float* __restrict__ beta,
          float* __restrict__ out)
{
    __shared__ float red1[8], red2[8];
    __shared__ float bmean, binv;

    const size_t row = blockIdx.x;
    const int tid = threadIdx.x;
    const int lane = tid & 31, wid = tid >> 5;
    const float* po = o + row * HIDDEN_;
    const float* pr = resid + row * HIDDEN_;

    float x[4];
    float s = 0.0f, s2 = 0.0f;
#pragma unroll
    for (int u = 0; u < 4; ++u) {
        const int idx = tid + 256 * u;
        x[u] = po[idx] + pr[idx];
        s += x[u];
        s2 += x[u] * x[u];
    }
#pragma unroll
    for (int of = 16; of; of >>= 1) {
        s  += __shfl_xor_sync(0xffffffffu, s,  of);
        s2 += __shfl_xor_sync(0xffffffffu, s2, of);
    }
    if (lane == 0) { red1[wid] = s; red2[wid] = s2; }
    __syncthreads();
    if (wid == 0) {
        float t1 = (lane < 8) ? red1[lane] : 0.0f;
        float t2 = (lane < 8) ? red2[lane] : 0.0f;
#pragma unroll
        for (int of = 16; of; of >>= 1) {
            t1 += __shfl_xor_sync(0xffffffffu, t1, of);
            t2 += __shfl_xor_sync(0xffffffffu, t2, of);
        }
        if (lane == 0) {
            const float mean = t1 * (1.0f / HIDDEN_);
            const float var  = t2 * (1.0f / HIDDEN_) - mean * mean;
            bmean = mean;
            binv  = rsqrtf(var + 1e-5f);
        }
    }
    __syncthreads();
    const float mean = bmean, inv = binv;
#pragma unroll
    for (int u = 0; u < 4; ++u) {
        const int idx = tid + 256 * u;
        out[row * HIDDEN_ + idx] = (x[u] - mean) * inv * gamma[idx] + beta[idx];
    }
}

// ---------------------------------------------------------------------------
static const int DSM_GEMM   = 4 * 128 * 36 * 4;                 // 73728
static const int DSM_SCORES = 2 * 128 * 68 * 4;                 // 69632
static const int DSM_CTX    = (2 * 128 * 36 + 2 * 64 * 36) * 4; // 55296

extern "C" void kernel_launch(void* const* d_in, const int* in_sizes, int n_in,
                              void* d_out, int out_size)
{
    const float* query = (const float*)d_in[0];
    const float* key_  = (const float*)d_in[1];
    const float* value = (const float*)d_in[2];
    const float* Wq = (const float*)d_in[3];
    const float* bq = (const float*)d_in[4];
    const float* Wk = (const float*)d_in[5];
    const float* bk = (const float*)d_in[6];
    const float* Wv = (const float*)d_in[7];
    const float* bv = (const float*)d_in[8];
    const float* Wo = (const float*)d_in[9];
    const float* bo = (const float*)d_in[10];
    const float* gamma = (const float*)d_in[11];
    const float* beta  = (const float*)d_in[12];
    const float* temp  = (const float*)d_in[13];

    cudaFuncSetAttribute(tc_gemm<true,  true, true >, cudaFuncAttributeMaxDynamicSharedMemorySize, DSM_GEMM);
    cudaFuncSetAttribute(tc_gemm<false, true, false>, cudaFuncAttributeMaxDynamicSharedMemorySize, DSM_GEMM);
    cudaFuncSetAttribute(scores_exp_kernel, cudaFuncAttributeMaxDynamicSharedMemorySize, DSM_SCORES);
    cudaFuncSetAttribute(ctx_fused_kernel,  cudaFuncAttributeMaxDynamicSharedMemorySize, DSM_CTX);

    float* out_ln = (float*)d_out;
    float *pQ, *pK, *pV, *pVT, *pCtx, *pO, *pE, *pPS, *pINV, *pP;
    cudaGetSymbolAddress((void**)&pQ,   g_Q);
    cudaGetSymbolAddress((void**)&pK,   g_K);
    cudaGetSymbolAddress((void**)&pV,   g_V);
    cudaGetSymbolAddress((void**)&pVT,  g_VT);
    cudaGetSymbolAddress((void**)&pCtx, g_ctx);
    cudaGetSymbolAddress((void**)&pO,   g_o);
    cudaGetSymbolAddress((void**)&pE,   g_E);
    cudaGetSymbolAddress((void**)&pPS,  g_PS);
    cudaGetSymbolAddress((void**)&pINV, g_INV);
    if ((long long)out_size >= LN_N + ATT_N) {
        pP = out_ln + LN_N;           // attn_weights are part of the output
    } else {
        pP = pE;                      // fallback: normalize E in place
    }

    // --- Projections: X @ W^T + b (in-frag RNA on A,B; outputs RNA-rounded)
    {
        dim3 g(HIDDEN_ / 128, MTOT_ / 128, 1);
        tc_gemm<true, true, true><<<g, 256, DSM_GEMM>>>(query, Wq, bq, pQ,
            HIDDEN_, HIDDEN_, HIDDEN_, HIDDEN_);
        tc_gemm<true, true, true><<<g, 256, DSM_GEMM>>>(key_,  Wk, bk, pK,
            HIDDEN_, HIDDEN_, HIDDEN_, HIDDEN_);
        tc_gemm<true, true, true><<<g, 256, DSM_GEMM>>>(value, Wv, bv, pV,
            HIDDEN_, HIDDEN_, HIDDEN_, HIDDEN_);
    }

    // --- VT: per-head transpose of V
    {
        dim3 g(SEQ_ / 32, HDIM_ / 32, BATCH_ * HEADS_);
        transpose_v_kernel<<<g, 256>>>(pV, pVT);
    }

    // --- Scores + exp + partial sums
    {
        dim3 g(SEQ_ / 128, SEQ_ / 128, BATCH_ * HEADS_);
        scores_exp_kernel<<<g, 256, DSM_SCORES>>>(pQ, pK, pE, pPS, temp);
    }

    // --- invl
    inv_reduce_kernel<<<NROWS_ / 256, 256>>>(pPS, pINV);

    // --- Context fused: P write + ctx mma
    {
        dim3 g(SEQ_ / 128, BATCH_ * HEADS_, 1);
        ctx_fused_kernel<<<g, 256, DSM_CTX>>>(pE, pINV, pVT, pP, pCtx);
    }

    // --- Output projection: o = ctx @ Wo^T + bo
    {
        dim3 g(HIDDEN_ / 128, MTOT_ / 128, 1);
        tc_gemm<false, true, false><<<g, 256, DSM_GEMM>>>(pCtx, Wo, bo, pO,
            HIDDEN_, HIDDEN_, HIDDEN_, HIDDEN_);
    }

    // --- Residual + LayerNorm
    ln_kernel<<<(unsigned)MTOT_, 256>>>(pO, query, gamma, beta, out_ln);
}